// round 1
// baseline (speedup 1.0000x reference)
#include <cuda_runtime.h>
#include <math.h>

#define LSEQ 262144
#define NMODE 64
#define TCH 128
#define NCHUNK (LSEQ / TCH)                 // 2048
#define WARPS_PER_BLOCK 8
#define BLOCK_THREADS (WARPS_PER_BLOCK * 32)
#define GRID_AC (NCHUNK / WARPS_PER_BLOCK)  // 256

// Per-mode constants (filled by setup_kernel, double-precision path)
__device__ float g_zre[NMODE], g_zim[NMODE];    // z = exp(dt*A)
__device__ float g_cfre[NMODE], g_cfim[NMODE];  // coeff = Ct*(z-1)/A
__device__ float g_wre[NMODE], g_wim[NMODE];    // w = z^TCH
// Chunk partials / carries: [mode][chunk]
__device__ float g_Pre[NMODE * NCHUNK], g_Pim[NMODE * NCHUNK];
__device__ float g_Cre[NMODE * NCHUNK], g_Cim[NMODE * NCHUNK];

__global__ void setup_kernel(const float* __restrict__ A_re,
                             const float* __restrict__ A_im,
                             const float* __restrict__ C,
                             const float* __restrict__ log_step) {
    int n = threadIdx.x;
    if (n >= NMODE) return;
    double dt  = exp((double)log_step[0]);
    double ar  = (double)A_re[n], ai = (double)A_im[n];
    double dre = dt * ar, dim = dt * ai;
    double e   = exp(dre);
    double zre = e * cos(dim), zim = e * sin(dim);
    // coeff = Ct * (z - 1) / A
    double nre = zre - 1.0, nim = zim;
    double inv = 1.0 / (ar * ar + ai * ai);
    double tre = (nre * ar + nim * ai) * inv;
    double tim = (nim * ar - nre * ai) * inv;
    double cr  = (double)C[2 * n], ci = (double)C[2 * n + 1];
    g_cfre[n] = (float)(cr * tre - ci * tim);
    g_cfim[n] = (float)(cr * tim + ci * tre);
    g_zre[n]  = (float)zre;
    g_zim[n]  = (float)zim;
    double ew = exp((double)TCH * dre);
    double wa = (double)TCH * dim;
    g_wre[n]  = (float)(ew * cos(wa));
    g_wim[n]  = (float)(ew * sin(wa));
}

// Phase 1: per-chunk local recurrence with zero init -> chunk partials.
// One warp per chunk; each lane owns modes (lane, lane+32).
__global__ __launch_bounds__(BLOCK_THREADS) void partial_kernel(const float* __restrict__ u) {
    __shared__ float su[WARPS_PER_BLOCK * TCH];
    int tid  = threadIdx.x;
    int base = blockIdx.x * (WARPS_PER_BLOCK * TCH);
#pragma unroll
    for (int i = 0; i < (WARPS_PER_BLOCK * TCH) / BLOCK_THREADS; i++)
        su[tid + i * BLOCK_THREADS] = u[base + tid + i * BLOCK_THREADS];
    __syncthreads();

    int warp = tid >> 5, lane = tid & 31;
    int chunk = blockIdx.x * WARPS_PER_BLOCK + warp;
    int m0 = lane, m1 = lane + 32;
    float z0r = g_zre[m0], z0i = g_zim[m0];
    float z1r = g_zre[m1], z1i = g_zim[m1];
    float s0r = 0.f, s0i = 0.f, s1r = 0.f, s1i = 0.f;
    const float* uw = &su[warp * TCH];
#pragma unroll 16
    for (int i = 0; i < TCH; i++) {
        float uv  = uw[i];
        float n0r = fmaf(z0r, s0r, fmaf(-z0i, s0i, uv));
        float n0i = fmaf(z0i, s0r, z0r * s0i);
        float n1r = fmaf(z1r, s1r, fmaf(-z1i, s1i, uv));
        float n1i = fmaf(z1i, s1r, z1r * s1i);
        s0r = n0r; s0i = n0i; s1r = n1r; s1i = n1i;
    }
    g_Pre[m0 * NCHUNK + chunk] = s0r;  g_Pim[m0 * NCHUNK + chunk] = s0i;
    g_Pre[m1 * NCHUNK + chunk] = s1r;  g_Pim[m1 * NCHUNK + chunk] = s1i;
}

// Phase 2: per-mode scan over 2048 chunk partials (constant coefficient w).
// Pairs 2 chunks per thread, Hillis-Steele over 1024 thread values with W = w^2.
__global__ __launch_bounds__(1024) void scan_kernel() {
    __shared__ float sre[1024], sim_[1024];
    int mode = blockIdx.x, t = threadIdx.x;
    float wr = g_wre[mode], wi = g_wim[mode];
    const float* Pr = &g_Pre[mode * NCHUNK];
    const float* Pi = &g_Pim[mode * NCHUNK];
    float p0r = Pr[2 * t],     p0i = Pi[2 * t];
    float p1r = Pr[2 * t + 1], p1i = Pi[2 * t + 1];
    // pair value v = w*p0 + p1  (inclusive through chunk 2t+1)
    float vr = fmaf(wr, p0r, fmaf(-wi, p0i, p1r));
    float vi = fmaf(wi, p0r, fmaf(wr, p0i, p1i));
    sre[t] = vr; sim_[t] = vi;
    float cwr = wr * wr - wi * wi, cwi = 2.f * wr * wi;  // W = w^2
    __syncthreads();
    for (int k = 1; k < 1024; k <<= 1) {
        float ore = 0.f, oim = 0.f;
        if (t >= k) { ore = sre[t - k]; oim = sim_[t - k]; }
        __syncthreads();
        vr += cwr * ore - cwi * oim;
        vi += cwr * oim + cwi * ore;
        sre[t] = vr; sim_[t] = vi;
        float nr = cwr * cwr - cwi * cwi;
        cwi = 2.f * cwr * cwi; cwr = nr;
        __syncthreads();
    }
    // Exclusive carries: Carry[c] = inclusive state through chunk c-1.
    float c0r = 0.f, c0i = 0.f;
    if (t > 0) { c0r = sre[t - 1]; c0i = sim_[t - 1]; }
    float* Cr = &g_Cre[mode * NCHUNK];
    float* Ci = &g_Cim[mode * NCHUNK];
    Cr[2 * t] = c0r;  Ci[2 * t] = c0i;
    float c1r = fmaf(wr, c0r, fmaf(-wi, c0i, p0r));
    float c1i = fmaf(wi, c0r, fmaf(wr, c0i, p0i));
    Cr[2 * t + 1] = c1r;  Ci[2 * t + 1] = c1i;
}

// Phase 3: re-run recurrence seeded with carries, emit y.
__global__ __launch_bounds__(BLOCK_THREADS) void output_kernel(const float* __restrict__ u,
                                                               const float* __restrict__ D,
                                                               float* __restrict__ y) {
    __shared__ float su[WARPS_PER_BLOCK * TCH];
    __shared__ float red[WARPS_PER_BLOCK][32 * 33];
    int tid  = threadIdx.x;
    int base = blockIdx.x * (WARPS_PER_BLOCK * TCH);
#pragma unroll
    for (int i = 0; i < (WARPS_PER_BLOCK * TCH) / BLOCK_THREADS; i++)
        su[tid + i * BLOCK_THREADS] = u[base + tid + i * BLOCK_THREADS];
    __syncthreads();

    int warp = tid >> 5, lane = tid & 31;
    int chunk = blockIdx.x * WARPS_PER_BLOCK + warp;
    int m0 = lane, m1 = lane + 32;
    float z0r = g_zre[m0], z0i = g_zim[m0];
    float z1r = g_zre[m1], z1i = g_zim[m1];
    float f0r = g_cfre[m0], f0i = g_cfim[m0];
    float f1r = g_cfre[m1], f1i = g_cfim[m1];
    float s0r = g_Cre[m0 * NCHUNK + chunk], s0i = g_Cim[m0 * NCHUNK + chunk];
    float s1r = g_Cre[m1 * NCHUNK + chunk], s1i = g_Cim[m1 * NCHUNK + chunk];
    float Dv = D[0];
    const float* uw = &su[warp * TCH];
    float* rw = &red[warp][0];
    int gbase = base + warp * TCH;

    for (int tile = 0; tile < TCH / 32; tile++) {
#pragma unroll
        for (int i = 0; i < 32; i++) {
            float uv  = uw[tile * 32 + i];
            float n0r = fmaf(z0r, s0r, fmaf(-z0i, s0i, uv));
            float n0i = fmaf(z0i, s0r, z0r * s0i);
            float n1r = fmaf(z1r, s1r, fmaf(-z1i, s1i, uv));
            float n1i = fmaf(z1i, s1r, z1r * s1i);
            s0r = n0r; s0i = n0i; s1r = n1r; s1i = n1i;
            // contribution of this lane's two modes: Re(coeff*s)
            float c = fmaf(f0r, s0r, fmaf(-f0i, s0i, fmaf(f1r, s1r, -f1i * s1i)));
            rw[lane * 33 + i] = c;  // bank-conflict-free (stride 33)
        }
        __syncwarp();
        float acc = 0.f;
#pragma unroll
        for (int l = 0; l < 32; l++) acc += rw[l * 33 + lane];
        float uv = uw[tile * 32 + lane];
        y[gbase + tile * 32 + lane] = fmaf(Dv, uv, acc);
        __syncwarp();
    }
}

extern "C" void kernel_launch(void* const* d_in, const int* in_sizes, int n_in,
                              void* d_out, int out_size) {
    const float* u        = (const float*)d_in[0];
    const float* A_re     = (const float*)d_in[1];
    const float* A_im     = (const float*)d_in[2];
    const float* C        = (const float*)d_in[3];
    const float* D        = (const float*)d_in[4];
    const float* log_step = (const float*)d_in[5];
    float* y = (float*)d_out;

    setup_kernel<<<1, NMODE>>>(A_re, A_im, C, log_step);
    partial_kernel<<<GRID_AC, BLOCK_THREADS>>>(u);
    scan_kernel<<<NMODE, 1024>>>();
    output_kernel<<<GRID_AC, BLOCK_THREADS>>>(u, D, y);
}